// round 1
// baseline (speedup 1.0000x reference)
#include <cuda_runtime.h>

#define N_NODES 8192
#define D_IN    512
#define D_OUT   256

// ---------------- scratch (device globals: no allocation allowed) ----------
static __device__ float g_wh[N_NODES * D_OUT];   // 8 MB
static __device__ float g_ssrc[N_NODES];
static __device__ float g_sdst[N_NODES];
static __device__ float g_E[N_NODES];            // exp(t_j)
static __device__ float g_F[N_NODES];            // exp(0.2 t_j)

// ---------------- packed f32x2 helpers (Blackwell) --------------------------
__device__ __forceinline__ unsigned long long pack2(float x, float y) {
    unsigned long long r;
    asm("mov.b64 %0, {%1, %2};" : "=l"(r)
        : "r"(__float_as_uint(x)), "r"(__float_as_uint(y)));
    return r;
}
__device__ __forceinline__ float2 unpack2(unsigned long long v) {
    unsigned int a, b;
    asm("mov.b64 {%0, %1}, %2;" : "=r"(a), "=r"(b) : "l"(v));
    return make_float2(__uint_as_float(a), __uint_as_float(b));
}
__device__ __forceinline__ unsigned long long ffma2(unsigned long long a,
                                                    unsigned long long b,
                                                    unsigned long long c) {
    unsigned long long d;
    asm("fma.rn.f32x2 %0, %1, %2, %3;" : "=l"(d) : "l"(a), "l"(b), "l"(c));
    return d;
}

// ==================== Kernel 1: wh = h @ W^T + b ============================
#define BM 128
#define BN 128
#define BK 16
#define TM 8
#define TN 8

__global__ void __launch_bounds__(256) gemm_wh_kernel(
    const float* __restrict__ h, const float* __restrict__ W,
    const float* __restrict__ Wb)
{
    __shared__ float As[BK][BM + 4];
    __shared__ float Bs[BK][BN + 4];
    const int tid = threadIdx.x;
    const int tx = tid & 15;   // 16 col groups
    const int ty = tid >> 4;   // 16 row groups
    const int row0 = blockIdx.y * BM;
    const int col0 = blockIdx.x * BN;

    float acc[TM][TN];
    #pragma unroll
    for (int i = 0; i < TM; i++)
        #pragma unroll
        for (int j = 0; j < TN; j++) acc[i][j] = 0.f;

    for (int kb = 0; kb < D_IN; kb += BK) {
        // 128x16 tiles of h and W, stored k-major in smem
        #pragma unroll
        for (int l = 0; l < 2; l++) {
            int f = tid + l * 256;       // float4 index 0..511
            int r = f >> 2;              // 0..127
            int c = (f & 3) << 2;        // 0,4,8,12
            float4 v = *(const float4*)&h[(size_t)(row0 + r) * D_IN + kb + c];
            As[c + 0][r] = v.x; As[c + 1][r] = v.y;
            As[c + 2][r] = v.z; As[c + 3][r] = v.w;
            float4 u = *(const float4*)&W[(size_t)(col0 + r) * D_IN + kb + c];
            Bs[c + 0][r] = u.x; Bs[c + 1][r] = u.y;
            Bs[c + 2][r] = u.z; Bs[c + 3][r] = u.w;
        }
        __syncthreads();
        #pragma unroll
        for (int k = 0; k < BK; k++) {
            float a[TM], b[TN];
            #pragma unroll
            for (int i = 0; i < TM; i++) a[i] = As[k][ty * TM + i];
            #pragma unroll
            for (int j = 0; j < TN; j++) b[j] = Bs[k][tx * TN + j];
            #pragma unroll
            for (int i = 0; i < TM; i++)
                #pragma unroll
                for (int j = 0; j < TN; j++)
                    acc[i][j] += a[i] * b[j];
        }
        __syncthreads();
    }

    #pragma unroll
    for (int i = 0; i < TM; i++) {
        int gr = row0 + ty * TM + i;
        #pragma unroll
        for (int j = 0; j < TN; j += 4) {
            int gc = col0 + tx * TN + j;
            float4 v;
            v.x = acc[i][j + 0] + Wb[gc + 0];
            v.y = acc[i][j + 1] + Wb[gc + 1];
            v.z = acc[i][j + 2] + Wb[gc + 2];
            v.w = acc[i][j + 3] + Wb[gc + 3];
            *(float4*)&g_wh[(size_t)gr * D_OUT + gc] = v;
        }
    }
}

// ==================== Kernel 2: per-row scores ==============================
// s_src[i] = wh[i]·a_src, t[i] = wh[i]·a_dst, E=exp(t), F=exp(0.2t)
__global__ void __launch_bounds__(256) scores_kernel(const float* __restrict__ aw)
{
    const int lane = threadIdx.x & 31;
    const int warp = threadIdx.x >> 5;
    const int row  = blockIdx.x * 8 + warp;

    const float4* whr = (const float4*)&g_wh[(size_t)row * D_OUT];
    float4 w0 = whr[lane * 2];
    float4 w1 = whr[lane * 2 + 1];
    const float4* as = (const float4*)aw;            // a_src (cols 0..255)
    const float4* ad = (const float4*)(aw + D_OUT);  // a_dst (cols 256..511)
    float4 a0 = as[lane * 2], a1 = as[lane * 2 + 1];
    float4 b0 = ad[lane * 2], b1 = ad[lane * 2 + 1];

    float ss = w0.x*a0.x + w0.y*a0.y + w0.z*a0.z + w0.w*a0.w
             + w1.x*a1.x + w1.y*a1.y + w1.z*a1.z + w1.w*a1.w;
    float sd = w0.x*b0.x + w0.y*b0.y + w0.z*b0.z + w0.w*b0.w
             + w1.x*b1.x + w1.y*b1.y + w1.z*b1.z + w1.w*b1.w;
    #pragma unroll
    for (int o = 16; o; o >>= 1) {
        ss += __shfl_xor_sync(0xffffffffu, ss, o);
        sd += __shfl_xor_sync(0xffffffffu, sd, o);
    }
    if (lane == 0) {
        g_ssrc[row] = ss;
        g_sdst[row] = sd;
        g_E[row] = __expf(sd);
        g_F[row] = __expf(0.2f * sd);
    }
}

// ==================== Kernel 3: masked softmax-attention ====================
// out[i] = (sum_j adj_ij * p_ij * wh[j]) / (sum_j adj_ij * p_ij)
// p_ij = (t_j > theta_i) ? alpha_i*E_j : beta_i*F_j   (exact softmax weights,
// shifted by M_i = lrelu(s_i + b + max_all t) which dominates every logit)
#define TJ  32
#define RPW 8          // rows per warp
#define RPB 64         // rows per block (8 warps)

__global__ void __launch_bounds__(256) flash_kernel(
    const int* __restrict__ adj, const float* __restrict__ abp,
    float* __restrict__ out)
{
    __shared__ __align__(16) float whs[TJ][D_OUT];   // 32 KB
    __shared__ float ts[TJ], Es[TJ], Fs[TJ];
    __shared__ float red[8];

    const int tid  = threadIdx.x;
    const int lane = tid & 31;
    const int warp = tid >> 5;

    // global max of t (same exact value in every block)
    float m = -3.0e38f;
    for (int i = tid; i < N_NODES; i += 256) m = fmaxf(m, g_sdst[i]);
    #pragma unroll
    for (int o = 16; o; o >>= 1) m = fmaxf(m, __shfl_xor_sync(0xffffffffu, m, o));
    if (lane == 0) red[warp] = m;
    __syncthreads();
    const float T = fmaxf(fmaxf(fmaxf(red[0], red[1]), fmaxf(red[2], red[3])),
                          fmaxf(fmaxf(red[4], red[5]), fmaxf(red[6], red[7])));

    const float ab = abp[0];
    const int rowbase = blockIdx.x * RPB + warp * RPW;

    float alpha[RPW], beta[RPW], theta[RPW], lsum[RPW];
    unsigned long long acc[RPW][4];
    #pragma unroll
    for (int rr = 0; rr < RPW; rr++) {
        float s  = g_ssrc[rowbase + rr] + ab;
        float Mh = s + T;
        float M  = Mh > 0.f ? Mh : 0.2f * Mh;   // lrelu(s + b + T)
        alpha[rr] = __expf(s - M);
        beta[rr]  = __expf(0.2f * s - M);
        theta[rr] = -s;
        lsum[rr]  = 0.f;
        acc[rr][0] = 0ull; acc[rr][1] = 0ull; acc[rr][2] = 0ull; acc[rr][3] = 0ull;
    }
    const int c0 = lane * 4;   // this lane owns cols [c0,c0+4) and [128+c0,128+c0+4)

    for (int jt = 0; jt < N_NODES; jt += TJ) {
        // stage wh tile (32 x 256 fp32)
        #pragma unroll
        for (int l = 0; l < 8; l++) {
            int f = tid + l * 256;       // float4 index 0..2047
            int j = f >> 6;              // 64 float4 per row
            int c = (f & 63) << 2;
            *(float4*)&whs[j][c] = *(const float4*)&g_wh[(size_t)(jt + j) * D_OUT + c];
        }
        if (tid < TJ) {
            ts[tid] = g_sdst[jt + tid];
            Es[tid] = g_E[jt + tid];
            Fs[tid] = g_F[jt + tid];
        }
        __syncthreads();

        // per-lane weight for column (jt + lane), for each of this warp's rows
        float p[RPW];
        #pragma unroll
        for (int rr = 0; rr < RPW; rr++) {
            int a = adj[(size_t)(rowbase + rr) * N_NODES + jt + lane];
            float pv = 0.f;
            if (a > 0)
                pv = (ts[lane] > theta[rr]) ? alpha[rr] * Es[lane]
                                            : beta[rr]  * Fs[lane];
            p[rr] = pv;
            lsum[rr] += pv;
        }

        // dense accumulation: acc += p_j * wh[j]
        #pragma unroll
        for (int j = 0; j < TJ; j++) {
            ulonglong2 wA = *(const ulonglong2*)&whs[j][c0];
            ulonglong2 wB = *(const ulonglong2*)&whs[j][128 + c0];
            #pragma unroll
            for (int rr = 0; rr < RPW; rr++) {
                float pj = __shfl_sync(0xffffffffu, p[rr], j);
                unsigned long long pp = pack2(pj, pj);
                acc[rr][0] = ffma2(pp, wA.x, acc[rr][0]);
                acc[rr][1] = ffma2(pp, wA.y, acc[rr][1]);
                acc[rr][2] = ffma2(pp, wB.x, acc[rr][2]);
                acc[rr][3] = ffma2(pp, wB.y, acc[rr][3]);
            }
        }
        __syncthreads();
    }

    #pragma unroll
    for (int rr = 0; rr < RPW; rr++) {
        float l = lsum[rr];
        #pragma unroll
        for (int o = 16; o; o >>= 1) l += __shfl_xor_sync(0xffffffffu, l, o);
        const float inv = 1.f / l;
        const int row = rowbase + rr;
        float2 r0 = unpack2(acc[rr][0]);
        float2 r1 = unpack2(acc[rr][1]);
        float2 r2 = unpack2(acc[rr][2]);
        float2 r3 = unpack2(acc[rr][3]);
        float4 o0 = make_float4(r0.x * inv, r0.y * inv, r1.x * inv, r1.y * inv);
        float4 o1 = make_float4(r2.x * inv, r2.y * inv, r3.x * inv, r3.y * inv);
        *(float4*)&out[(size_t)row * D_OUT + c0]       = o0;
        *(float4*)&out[(size_t)row * D_OUT + 128 + c0] = o1;
    }
}

// ==================== launch ================================================
extern "C" void kernel_launch(void* const* d_in, const int* in_sizes, int n_in,
                              void* d_out, int out_size)
{
    const float* h   = (const float*)d_in[0];
    const int*   adj = (const int*)  d_in[1];
    const float* Ww  = (const float*)d_in[2];
    const float* Wb  = (const float*)d_in[3];
    const float* aw  = (const float*)d_in[4];
    const float* ab  = (const float*)d_in[5];
    float* out = (float*)d_out;

    gemm_wh_kernel<<<dim3(D_OUT / BN, N_NODES / BM), 256>>>(h, Ww, Wb);
    scores_kernel<<<N_NODES / 8, 256>>>(aw);
    flash_kernel<<<N_NODES / RPB, 256>>>(adj, ab, out);
}

// round 3
// speedup vs baseline: 2.7387x; 2.7387x over previous
#include <cuda_runtime.h>
#include <cuda_fp16.h>
#include <cstdint>

#define N_NODES 8192
#define D_IN    512
#define D_OUT   256
#define KC      128
#define NCH     (N_NODES / KC)
#define MT      64            // rows per CTA in flash
#define THREADS 512

// ---------------- scratch (device globals) ----------------------------------
static __device__ float  g_wh [N_NODES * D_OUT];      // fp32 wh (8 MB)
static __device__ __half g_whT[D_OUT * N_NODES];      // fp16 wh^T (4 MB)
static __device__ float  g_ssrc[N_NODES];
static __device__ float  g_sdst[N_NODES];
static __device__ float  g_E[N_NODES];
static __device__ float  g_F[N_NODES];

// ---------------- PTX helpers -----------------------------------------------
__device__ __forceinline__ uint32_t smem_u32(const void* p) {
    uint32_t a;
    asm("{ .reg .u64 t; cvta.to.shared.u64 t, %1; cvt.u32.u64 %0, t; }"
        : "=r"(a) : "l"(p));
    return a;
}
__device__ __forceinline__ void ldmatrix_x4(uint32_t& r0, uint32_t& r1,
                                            uint32_t& r2, uint32_t& r3,
                                            uint32_t addr) {
    asm volatile("ldmatrix.sync.aligned.m8n8.x4.shared.b16 {%0,%1,%2,%3}, [%4];"
                 : "=r"(r0), "=r"(r1), "=r"(r2), "=r"(r3) : "r"(addr));
}
__device__ __forceinline__ void mma16816(float& c0, float& c1, float& c2, float& c3,
                                         uint32_t a0, uint32_t a1, uint32_t a2, uint32_t a3,
                                         uint32_t b0, uint32_t b1) {
    asm volatile("mma.sync.aligned.m16n8k16.row.col.f32.f16.f16.f32 "
                 "{%0,%1,%2,%3}, {%4,%5,%6,%7}, {%8,%9}, {%0,%1,%2,%3};"
                 : "+f"(c0), "+f"(c1), "+f"(c2), "+f"(c3)
                 : "r"(a0), "r"(a1), "r"(a2), "r"(a3), "r"(b0), "r"(b1));
}

// ==================== Kernel 1: wh = h @ W^T + b (fp32 SIMT) ================
#define BM 128
#define BN 128
#define BK 16
#define TM 8
#define TN 8

__global__ void __launch_bounds__(256) gemm_wh_kernel(
    const float* __restrict__ h, const float* __restrict__ W,
    const float* __restrict__ Wb)
{
    __shared__ float As[BK][BM + 4];
    __shared__ float Bs[BK][BN + 4];
    const int tid = threadIdx.x;
    const int tx = tid & 15;
    const int ty = tid >> 4;
    const int row0 = blockIdx.y * BM;
    const int col0 = blockIdx.x * BN;

    float acc[TM][TN];
    #pragma unroll
    for (int i = 0; i < TM; i++)
        #pragma unroll
        for (int j = 0; j < TN; j++) acc[i][j] = 0.f;

    for (int kb = 0; kb < D_IN; kb += BK) {
        #pragma unroll
        for (int l = 0; l < 2; l++) {
            int f = tid + l * 256;
            int r = f >> 2;
            int c = (f & 3) << 2;
            float4 v = *(const float4*)&h[(size_t)(row0 + r) * D_IN + kb + c];
            As[c + 0][r] = v.x; As[c + 1][r] = v.y;
            As[c + 2][r] = v.z; As[c + 3][r] = v.w;
            float4 u = *(const float4*)&W[(size_t)(col0 + r) * D_IN + kb + c];
            Bs[c + 0][r] = u.x; Bs[c + 1][r] = u.y;
            Bs[c + 2][r] = u.z; Bs[c + 3][r] = u.w;
        }
        __syncthreads();
        #pragma unroll
        for (int k = 0; k < BK; k++) {
            float a[TM], b[TN];
            #pragma unroll
            for (int i = 0; i < TM; i++) a[i] = As[k][ty * TM + i];
            #pragma unroll
            for (int j = 0; j < TN; j++) b[j] = Bs[k][tx * TN + j];
            #pragma unroll
            for (int i = 0; i < TM; i++)
                #pragma unroll
                for (int j = 0; j < TN; j++)
                    acc[i][j] += a[i] * b[j];
        }
        __syncthreads();
    }

    #pragma unroll
    for (int i = 0; i < TM; i++) {
        int gr = row0 + ty * TM + i;
        #pragma unroll
        for (int j = 0; j < TN; j += 4) {
            int gc = col0 + tx * TN + j;
            float4 v;
            v.x = acc[i][j + 0] + Wb[gc + 0];
            v.y = acc[i][j + 1] + Wb[gc + 1];
            v.z = acc[i][j + 2] + Wb[gc + 2];
            v.w = acc[i][j + 3] + Wb[gc + 3];
            *(float4*)&g_wh[(size_t)gr * D_OUT + gc] = v;
        }
    }
}

// ==================== Kernel 1b: whT fp16 = transpose(wh) ===================
__global__ void __launch_bounds__(256) transpose_wh_kernel()
{
    __shared__ __half tile[32][33];
    const int tx = threadIdx.x & 31;
    const int ty = threadIdx.x >> 5;
    const int c0 = blockIdx.x * 32;
    const int r0 = blockIdx.y * 32;
    #pragma unroll
    for (int i = 0; i < 4; i++) {
        int rr = ty + i * 8;
        tile[rr][tx] = __float2half(g_wh[(size_t)(r0 + rr) * D_OUT + c0 + tx]);
    }
    __syncthreads();
    #pragma unroll
    for (int i = 0; i < 4; i++) {
        int cc = ty + i * 8;
        g_whT[(size_t)(c0 + cc) * N_NODES + r0 + tx] = tile[tx][cc];
    }
}

// ==================== Kernel 2: per-row scores ==============================
__global__ void __launch_bounds__(256) scores_kernel(const float* __restrict__ aw)
{
    const int lane = threadIdx.x & 31;
    const int warp = threadIdx.x >> 5;
    const int row  = blockIdx.x * 8 + warp;

    const float4* whr = (const float4*)&g_wh[(size_t)row * D_OUT];
    float4 w0 = whr[lane * 2];
    float4 w1 = whr[lane * 2 + 1];
    const float4* as = (const float4*)aw;
    const float4* ad = (const float4*)(aw + D_OUT);
    float4 a0 = as[lane * 2], a1 = as[lane * 2 + 1];
    float4 b0 = ad[lane * 2], b1 = ad[lane * 2 + 1];

    float ss = w0.x*a0.x + w0.y*a0.y + w0.z*a0.z + w0.w*a0.w
             + w1.x*a1.x + w1.y*a1.y + w1.z*a1.z + w1.w*a1.w;
    float sd = w0.x*b0.x + w0.y*b0.y + w0.z*b0.z + w0.w*b0.w
             + w1.x*b1.x + w1.y*b1.y + w1.z*b1.z + w1.w*b1.w;
    #pragma unroll
    for (int o = 16; o; o >>= 1) {
        ss += __shfl_xor_sync(0xffffffffu, ss, o);
        sd += __shfl_xor_sync(0xffffffffu, sd, o);
    }
    if (lane == 0) {
        g_ssrc[row] = ss;
        g_sdst[row] = sd;
        g_E[row] = __expf(sd);
        g_F[row] = __expf(0.2f * sd);
    }
}

// ==================== Kernel 3: HMMA flash ==================================
// SMEM (dynamic, bytes):
//   Bs: whT tile  [256][136] fp16   @ 0       (69632)
//   As: P tile    [ 64][136] fp16   @ 69632   (17408)
//   ts/Es/Fs: 3x128 fp32            @ 87040   (1536)
//   lsum: 64 fp32 (+max red reuse)  @ 88576   (256)
#define LDB 136
static constexpr uint32_t BS_OFF = 0;
static constexpr uint32_t AS_OFF = 69632;
static constexpr uint32_t SC_OFF = 87040;
static constexpr uint32_t LS_OFF = 88576;
static constexpr uint32_t SMEM_TOTAL = 88832;

__global__ void __launch_bounds__(THREADS) flash_mma_kernel(
    const int* __restrict__ adj, const float* __restrict__ abp,
    float* __restrict__ out)
{
    extern __shared__ __align__(16) char smem[];
    __half* Bs = (__half*)(smem + BS_OFF);
    __half* As = (__half*)(smem + AS_OFF);
    float*  ts = (float*)(smem + SC_OFF);
    float*  Es = ts + 128;
    float*  Fs = ts + 256;
    float*  lsum_s = (float*)(smem + LS_OFF);

    const int tid  = threadIdx.x;
    const int lane = tid & 31;
    const int warp = tid >> 5;
    const int rowbase = blockIdx.x * MT;

    // ---- global max of t ----
    float m = -3.0e38f;
    for (int i = tid; i < N_NODES; i += THREADS) m = fmaxf(m, g_sdst[i]);
    #pragma unroll
    for (int o = 16; o; o >>= 1) m = fmaxf(m, __shfl_xor_sync(0xffffffffu, m, o));
    if (lane == 0) lsum_s[warp] = m;
    __syncthreads();
    float T = lsum_s[0];
    #pragma unroll
    for (int w = 1; w < 16; w++) T = fmaxf(T, lsum_s[w]);
    __syncthreads();

    // ---- per-thread row constants (row = tid/8, j-segment = tid%8) ----
    const float ab = abp[0];
    const int prow = tid >> 3;           // 0..63
    const int pseg = tid & 7;            // 16 j's each
    {
        // silence unused in case MT changes
    }
    const float s  = g_ssrc[rowbase + prow] + ab;
    const float Mh = s + T;
    const float M  = Mh > 0.f ? Mh : 0.2f * Mh;
    const float alpha = __expf(s - M);
    const float beta  = __expf(0.2f * s - M);
    const float theta = -s;
    float lpriv = 0.f;

    // ---- mma per-warp setup ----
    const uint32_t as_u = smem_u32(As);
    const uint32_t bs_u = smem_u32(Bs);
    const int nslab = warp * 16;
    // A ldmatrix lane address: row = lane%16, col-half = (lane/16)*8
    const uint32_t a_lane = as_u + (uint32_t)(((lane & 15) * LDB + (lane >> 4) * 8) * 2);
    // B ldmatrix lane address: n = nslab + lane%8 + (lane/16)*8, koff = ((lane>>3)&1)*8
    const uint32_t b_lane = bs_u + (uint32_t)((((nslab + (lane & 7) + ((lane >> 4) << 3)) * LDB)
                                               + (((lane >> 3) & 1) << 3)) * 2);

    float acc[4][2][4];
    #pragma unroll
    for (int mi = 0; mi < 4; mi++)
        #pragma unroll
        for (int ni = 0; ni < 2; ni++)
            #pragma unroll
            for (int u = 0; u < 4; u++) acc[mi][ni][u] = 0.f;

    const int4* adjrow = (const int4*)(adj + (size_t)(rowbase + prow) * N_NODES);

    for (int kt = 0; kt < NCH; kt++) {
        const int k0 = kt << 7;

        // ---- stage Bs: 256 n x 128 k fp16 ----
        #pragma unroll
        for (int i = 0; i < 8; i++) {
            int flat = tid + (i << 9);       // uint4 index 0..4095
            int n = flat >> 4;
            int c = flat & 15;
            uint4 v = *(const uint4*)(g_whT + (size_t)n * N_NODES + k0 + c * 8);
            *(uint4*)(Bs + n * LDB + c * 8) = v;
        }
        // ---- stage scalars ----
        if (tid < 128) {
            ts[tid] = g_sdst[k0 + tid];
            Es[tid] = g_E[k0 + tid];
            Fs[tid] = g_F[k0 + tid];
        }
        __syncthreads();

        // ---- P-gen: 16 weights for (prow, j in [k0+pseg*16, +16)) ----
        {
            const int4* ap = adjrow + (k0 >> 2) + pseg * 4;
            uint4 w0, w1;
            uint32_t* wp = (uint32_t*)&w0;
            #pragma unroll
            for (int it = 0; it < 4; it++) {
                int4 q = ap[it];
                int jb = pseg * 16 + it * 4;
                float4 t4 = *(float4*)(ts + jb);
                float4 e4 = *(float4*)(Es + jb);
                float4 f4 = *(float4*)(Fs + jb);
                float p0 = q.x > 0 ? (t4.x > theta ? alpha * e4.x : beta * f4.x) : 0.f;
                float p1 = q.y > 0 ? (t4.y > theta ? alpha * e4.y : beta * f4.y) : 0.f;
                float p2 = q.z > 0 ? (t4.z > theta ? alpha * e4.z : beta * f4.z) : 0.f;
                float p3 = q.w > 0 ? (t4.w > theta ? alpha * e4.w : beta * f4.w) : 0.f;
                lpriv += (p0 + p1) + (p2 + p3);
                __half2 h0 = __floats2half2_rn(p0, p1);
                __half2 h1 = __floats2half2_rn(p2, p3);
                if (it == 2) wp = (uint32_t*)&w1;
                wp[(it & 1) * 2 + 0] = *(uint32_t*)&h0;
                wp[(it & 1) * 2 + 1] = *(uint32_t*)&h1;
            }
            *(uint4*)(As + prow * LDB + pseg * 16)     = w0;
            *(uint4*)(As + prow * LDB + pseg * 16 + 8) = w1;
        }
        __syncthreads();

        // ---- MMA: 8 k-steps, 4 m-tiles, 2 n-tiles ----
        #pragma unroll
        for (int k = 0; k < 8; k++) {
            uint32_t b0, b1, b2, b3;
            ldmatrix_x4(b0, b1, b2, b3, b_lane + (uint32_t)(k * 16 * 2));
            #pragma unroll
            for (int mi = 0; mi < 4; mi++) {
                uint32_t a0, a1, a2, a3;
                ldmatrix_x4(a0, a1, a2, a3,
                            a_lane + (uint32_t)((mi * 16 * LDB + k * 16) * 2));
                mma16816(acc[mi][0][0], acc[mi][0][1], acc[mi][0][2], acc[mi][0][3],
                         a0, a1, a2, a3, b0, b1);
                mma16816(acc[mi][1][0], acc[mi][1][1], acc[mi][1][2], acc[mi][1][3],
                         a0, a1, a2, a3, b2, b3);
            }
        }
        __syncthreads();
    }

    // ---- lsum: reduce over the 8 threads sharing a row ----
    lpriv += __shfl_xor_sync(0xffffffffu, lpriv, 1);
    lpriv += __shfl_xor_sync(0xffffffffu, lpriv, 2);
    lpriv += __shfl_xor_sync(0xffffffffu, lpriv, 4);
    if ((lane & 7) == 0) lsum_s[prow] = lpriv;
    __syncthreads();

    // ---- write out: out[row][col] = acc / lsum ----
    #pragma unroll
    for (int mi = 0; mi < 4; mi++) {
        int r0 = mi * 16 + (lane >> 2);
        int r1 = r0 + 8;
        float inv0 = 1.f / lsum_s[r0];
        float inv1 = 1.f / lsum_s[r1];
        #pragma unroll
        for (int ni = 0; ni < 2; ni++) {
            int c = nslab + ni * 8 + ((lane & 3) << 1);
            float2 v0 = make_float2(acc[mi][ni][0] * inv0, acc[mi][ni][1] * inv0);
            float2 v1 = make_float2(acc[mi][ni][2] * inv1, acc[mi][ni][3] * inv1);
            *(float2*)&out[(size_t)(rowbase + r0) * D_OUT + c] = v0;
            *(float2*)&out[(size_t)(rowbase + r1) * D_OUT + c] = v1;
        }
    }
}

// ==================== launch ================================================
extern "C" void kernel_launch(void* const* d_in, const int* in_sizes, int n_in,
                              void* d_out, int out_size)
{
    const float* h   = (const float*)d_in[0];
    const int*   adj = (const int*)  d_in[1];
    const float* Ww  = (const float*)d_in[2];
    const float* Wb  = (const float*)d_in[3];
    const float* aw  = (const float*)d_in[4];
    const float* ab  = (const float*)d_in[5];
    float* out = (float*)d_out;

    cudaFuncSetAttribute(flash_mma_kernel,
                         cudaFuncAttributeMaxDynamicSharedMemorySize, SMEM_TOTAL);

    gemm_wh_kernel<<<dim3(D_OUT / BN, N_NODES / BM), 256>>>(h, Ww, Wb);
    transpose_wh_kernel<<<dim3(D_OUT / 32, N_NODES / 32), 256>>>();
    scores_kernel<<<N_NODES / 8, 256>>>(aw);
    flash_mma_kernel<<<N_NODES / MT, THREADS, SMEM_TOTAL>>>(adj, ab, out);
}